// round 1
// baseline (speedup 1.0000x reference)
#include <cuda_runtime.h>
#include <cuda_bf16.h>
#include <math.h>

// ---- Physical constants, folded at compile time (double precision, cast once) ----
namespace mk {
constexpr double R_      = 3.0 * 0.0254;                 // wheel radius
constexpr double LSUM    = 0.129907 + 0.095724;          // L_X + L_Y
constexpr double G_      = 13.7;
constexpr double MASS_   = 12.0;
constexpr double MOI_    = MASS_ * (12.0 * 0.0254) * (12.0 * 0.0254) / 6.0;

// wheel_vel coefficients (LOCAL_TO_WHEEL_ROT entries)
constexpr float INV_R = (float)(1.0 / R_);
constexpr float L_R   = (float)(LSUM / R_);
// torque coefficients
constexpr float T_DUTY = (float)(0.193 * G_);            // motor_duty * 0.193 * G
constexpr float T_VEL  = (float)(G_ * 0.000304 * G_);    // wheel_vel * G*3.04e-4 * G
constexpr float T_FRIC = (float)(0.00317 * G_);          // softsign * 0.00317 * G
// pinv-derived local-accel coefficients
constexpr float K_XY = (float)(1.0 / (4.0 * R_ * MASS_));
constexpr float K_W  = (float)(1.0 / (4.0 * LSUM * R_ * MOI_));
constexpr float EPS  = 0.01f;
}

// Compute one row: inputs (theta, vx, vy, w, u0, u1, u2) -> (ax, ay, aw)
__device__ __forceinline__ void mecanum_row(
    float theta, float vx, float vy, float wz,
    float u0, float u1, float u2,
    float& ax, float& ay, float& aw)
{
    float st, ct;
    sincosf(theta, &st, &ct);

    // local velocity (rotation by -theta)
    float lvx =  ct * vx + st * vy;
    float lvy = -st * vx + ct * vy;

    // wheel velocities
    float p = mk::INV_R * (lvx + lvy);
    float m = mk::INV_R * (lvx - lvy);
    float lz = mk::L_R * wz;
    float w0 = m - lz;
    float w1 = p + lz;
    float w2 = p - lz;
    float w3 = m + lz;

    // motor duty
    float m0 = u0 - u1 - u2;
    float m1 = u0 + u1 + u2;
    float m2 = u0 + u1 - u2;
    float m3 = u0 - u1 + u2;

    // wheel torque: (duty*0.193 - wvel*G*3.04e-4 - softsign(wvel)*3.17e-3) * G
    float ss0 = w0 * rsqrtf(w0 * w0 + mk::EPS);
    float ss1 = w1 * rsqrtf(w1 * w1 + mk::EPS);
    float ss2 = w2 * rsqrtf(w2 * w2 + mk::EPS);
    float ss3 = w3 * rsqrtf(w3 * w3 + mk::EPS);
    float t0 = mk::T_DUTY * m0 - mk::T_VEL * w0 - mk::T_FRIC * ss0;
    float t1 = mk::T_DUTY * m1 - mk::T_VEL * w1 - mk::T_FRIC * ss1;
    float t2 = mk::T_DUTY * m2 - mk::T_VEL * w2 - mk::T_FRIC * ss2;
    float t3 = mk::T_DUTY * m3 - mk::T_VEL * w3 - mk::T_FRIC * ss3;

    // local acceleration (analytic pinv)
    float la0 = mk::K_XY * ( t0 + t1 + t2 + t3);
    float la1 = mk::K_XY * (-t0 + t1 + t2 - t3);
    float la2 = mk::K_W  * (-t0 + t1 - t2 + t3);

    // rotate back by +theta (A^T)
    ax = ct * la0 - st * la1;
    ay = st * la0 + ct * la1;
    aw = la2;
}

// Fast path: 4 rows per thread, all memory traffic as float4 (16B) transactions.
// state rows: 24 floats = 6 x float4; control: 12 floats = 3 x float4; out: 6 x float4.
__global__ void __launch_bounds__(256)
mecanum4_kernel(const float4* __restrict__ st4,
                const float4* __restrict__ cd4,
                float4* __restrict__ out4,
                int ngroups)
{
    int g = blockIdx.x * blockDim.x + threadIdx.x;
    if (g >= ngroups) return;

    float s[24], u[12], o[24];
    float4* sv = reinterpret_cast<float4*>(s);
    float4* uv = reinterpret_cast<float4*>(u);
    float4* ov = reinterpret_cast<float4*>(o);

    const float4* sp = st4 + 6 * (size_t)g;
    const float4* cp = cd4 + 3 * (size_t)g;
#pragma unroll
    for (int k = 0; k < 6; k++) sv[k] = sp[k];
#pragma unroll
    for (int k = 0; k < 3; k++) uv[k] = cp[k];

#pragma unroll
    for (int r = 0; r < 4; r++) {
        float theta = s[6 * r + 2];
        float vx = s[6 * r + 3], vy = s[6 * r + 4], wz = s[6 * r + 5];
        float ax, ay, aw;
        mecanum_row(theta, vx, vy, wz,
                    u[3 * r + 0], u[3 * r + 1], u[3 * r + 2],
                    ax, ay, aw);
        o[6 * r + 0] = vx;
        o[6 * r + 1] = vy;
        o[6 * r + 2] = wz;
        o[6 * r + 3] = ax;
        o[6 * r + 4] = ay;
        o[6 * r + 5] = aw;
    }

    float4* op = out4 + 6 * (size_t)g;
#pragma unroll
    for (int k = 0; k < 6; k++) op[k] = ov[k];
}

// Scalar fallback (any B, used only if B % 4 != 0)
__global__ void __launch_bounds__(256)
mecanum1_kernel(const float* __restrict__ state,
                const float* __restrict__ ctrl,
                float* __restrict__ out,
                int B)
{
    int i = blockIdx.x * blockDim.x + threadIdx.x;
    if (i >= B) return;
    const float* s = state + 6 * (size_t)i;
    const float* u = ctrl + 3 * (size_t)i;
    float* o = out + 6 * (size_t)i;
    float ax, ay, aw;
    mecanum_row(s[2], s[3], s[4], s[5], u[0], u[1], u[2], ax, ay, aw);
    o[0] = s[3]; o[1] = s[4]; o[2] = s[5];
    o[3] = ax;   o[4] = ay;   o[5] = aw;
}

extern "C" void kernel_launch(void* const* d_in, const int* in_sizes, int n_in,
                              void* d_out, int out_size)
{
    // metadata order: t (1), state (B*6), control_duty (B*3)
    const float* state = (const float*)d_in[1];
    const float* ctrl  = (const float*)d_in[2];
    float* out = (float*)d_out;
    int B = in_sizes[1] / 6;

    if ((B & 3) == 0) {
        int ng = B >> 2;
        int threads = 256;
        int blocks = (ng + threads - 1) / threads;
        mecanum4_kernel<<<blocks, threads>>>(
            (const float4*)state, (const float4*)ctrl, (float4*)out, ng);
    } else {
        int threads = 256;
        int blocks = (B + threads - 1) / threads;
        mecanum1_kernel<<<blocks, threads>>>(state, ctrl, out, B);
    }
}